// round 5
// baseline (speedup 1.0000x reference)
#include <cuda_runtime.h>
#include <cuda_bf16.h>
#include <math.h>
#include <cstdint>

#define NB      4096
#define PAD     (NB / 2)
#define BATCH   8192
#define T       512
#define NWARP   (T / 32)          // 16
#define GRID_N  592               // 148 SMs * 4 CTAs/SM

// ---------------------------------------------------------------------------
// Single fused kernel.
//  Prologue (per CTA): p = sigmoid(logits) into registers (8/thread),
//    l as bf16x2 registers, C = sum log_sigmoid(-l) block-reduced into smem.
//  Loop (1 row / CTA-iteration, grid-stride):
//    compare -> byte-packed grid in double-buffered smem + weighted sum,
//    prefetch next row's u BEFORE the barrier (latency overlaps gather),
//    reflect-shift gather via LDS + byte_perm -> STG.128.
// ---------------------------------------------------------------------------
__global__ __launch_bounds__(T, 4)
void fused_kernel(const float* __restrict__ logits,
                  const float* __restrict__ u,
                  const int*   __restrict__ shift,
                  float*       __restrict__ masks,
                  float*       __restrict__ log_probs) {
    __shared__ __align__(16) unsigned char s_g[2][NB + 16];
    __shared__ float s_red[2][NWARP];
    __shared__ float s_C;

    const int tid  = threadIdx.x;
    const int lane = tid & 31;
    const int warp = tid >> 5;

    // ---- prologue: per-thread row-invariant p, l; block constant C ----------
    const float4* __restrict__ l4 = (const float4*)logits;
    const float4 La = l4[tid];
    const float4 Lb = l4[tid + T];

    float4 pa, pb;
    pa.x = 1.0f / (1.0f + expf(-La.x));
    pa.y = 1.0f / (1.0f + expf(-La.y));
    pa.z = 1.0f / (1.0f + expf(-La.z));
    pa.w = 1.0f / (1.0f + expf(-La.w));
    pb.x = 1.0f / (1.0f + expf(-Lb.x));
    pb.y = 1.0f / (1.0f + expf(-Lb.y));
    pb.z = 1.0f / (1.0f + expf(-Lb.z));
    pb.w = 1.0f / (1.0f + expf(-Lb.w));

    const __nv_bfloat162 la0 = __floats2bfloat162_rn(La.x, La.y);
    const __nv_bfloat162 la1 = __floats2bfloat162_rn(La.z, La.w);
    const __nv_bfloat162 lb0 = __floats2bfloat162_rn(Lb.x, Lb.y);
    const __nv_bfloat162 lb1 = __floats2bfloat162_rn(Lb.z, Lb.w);

    {   // C = sum_j -(log1p(exp(-|l_j|)) + max(l_j, 0))
        float c = 0.0f;
        c -= log1pf(expf(-fabsf(La.x))) + fmaxf(La.x, 0.0f);
        c -= log1pf(expf(-fabsf(La.y))) + fmaxf(La.y, 0.0f);
        c -= log1pf(expf(-fabsf(La.z))) + fmaxf(La.z, 0.0f);
        c -= log1pf(expf(-fabsf(La.w))) + fmaxf(La.w, 0.0f);
        c -= log1pf(expf(-fabsf(Lb.x))) + fmaxf(Lb.x, 0.0f);
        c -= log1pf(expf(-fabsf(Lb.y))) + fmaxf(Lb.y, 0.0f);
        c -= log1pf(expf(-fabsf(Lb.z))) + fmaxf(Lb.z, 0.0f);
        c -= log1pf(expf(-fabsf(Lb.w))) + fmaxf(Lb.w, 0.0f);
        #pragma unroll
        for (int o = 16; o; o >>= 1) c += __shfl_xor_sync(0xFFFFFFFFu, c, o);
        if (lane == 0) s_red[0][warp] = c;
        __syncthreads();
        if (tid == 0) {
            float v = 0.0f;
            #pragma unroll
            for (int i = 0; i < NWARP; i++) v += s_red[0][i];
            s_C = v;
        }
        __syncthreads();
    }
    const float cC = s_C;

    // ---- main loop: software-pipelined over rows -----------------------------
    int b   = blockIdx.x;
    int buf = 0;
    float4 ua = __ldcs(&((const float4*)(u + (size_t)b * NB))[tid]);
    float4 ub = __ldcs(&((const float4*)(u + (size_t)b * NB))[tid + T]);
    int    sh = __ldg(&shift[b]);

    while (b < BATCH) {
        // grid bits + weighted sum
        uint32_t wa = (ua.x < pa.x ? 0x01u      : 0u)
                    | (ua.y < pa.y ? 0x100u     : 0u)
                    | (ua.z < pa.z ? 0x10000u   : 0u)
                    | (ua.w < pa.w ? 0x1000000u : 0u);
        uint32_t wb = (ub.x < pb.x ? 0x01u      : 0u)
                    | (ub.y < pb.y ? 0x100u     : 0u)
                    | (ub.z < pb.z ? 0x10000u   : 0u)
                    | (ub.w < pb.w ? 0x1000000u : 0u);
        float acc = (ua.x < pa.x ? __low2float(la0)  : 0.0f)
                  + (ua.y < pa.y ? __high2float(la0) : 0.0f)
                  + (ua.z < pa.z ? __low2float(la1)  : 0.0f)
                  + (ua.w < pa.w ? __high2float(la1) : 0.0f)
                  + (ub.x < pb.x ? __low2float(lb0)  : 0.0f)
                  + (ub.y < pb.y ? __high2float(lb0) : 0.0f)
                  + (ub.z < pb.z ? __low2float(lb1)  : 0.0f)
                  + (ub.w < pb.w ? __high2float(lb1) : 0.0f);

        uint32_t* sw = (uint32_t*)&s_g[buf][0];
        sw[tid]     = wa;
        sw[tid + T] = wb;

        #pragma unroll
        for (int o = 16; o; o >>= 1) acc += __shfl_xor_sync(0xFFFFFFFFu, acc, o);
        if (lane == 0) s_red[buf][warp] = acc;

        // prefetch next row BEFORE the barrier: DRAM latency overlaps gather
        const int bn = b + GRID_N;
        float4 na = make_float4(0.f, 0.f, 0.f, 0.f);
        float4 nb = make_float4(0.f, 0.f, 0.f, 0.f);
        int    nsh = 0;
        if (bn < BATCH) {
            na  = __ldcs(&((const float4*)(u + (size_t)bn * NB))[tid]);
            nb  = __ldcs(&((const float4*)(u + (size_t)bn * NB))[tid + T]);
            nsh = __ldg(&shift[bn]);
        }

        __syncthreads();

        if (warp == 0) {
            float v = (lane < NWARP) ? s_red[buf][lane] : 0.0f;
            #pragma unroll
            for (int o = 8; o; o >>= 1) v += __shfl_xor_sync(0xFFFFFFFFu, v, o);
            if (lane == 0) log_probs[b] = v + cC;
        }

        // reflect-shift gather -> 2x STG.128
        float4* __restrict__ out4 = (float4*)(masks + (size_t)b * NB);
        #pragma unroll
        for (int it = 0; it < 2; ++it) {
            const int j0   = 4 * (tid + it * T);
            const int base = sh + j0 - PAD;
            float4 o4;
            if (base >= 0 && base <= NB - 4) {
                const int wi = base >> 2;
                uint32_t w0 = sw[wi], w1 = sw[wi + 1];        // wi+1 within padding
                uint32_t pk = __byte_perm(w0, w1, 0x3210 + (base & 3) * 0x1111);
                o4.x = __int_as_float((pk & 0xFFu)         * 0x3F800000u);
                o4.y = __int_as_float(((pk >> 8)  & 0xFFu) * 0x3F800000u);
                o4.z = __int_as_float(((pk >> 16) & 0xFFu) * 0x3F800000u);
                o4.w = __int_as_float(((pk >> 24) & 0xFFu) * 0x3F800000u);
            } else {
                float r[4];
                #pragma unroll
                for (int k = 0; k < 4; k++) {
                    int s = base + k;
                    s = (s < 0) ? -s : s;
                    s = (s >= NB) ? (2 * (NB - 1) - s) : s;
                    r[k] = (float)s_g[buf][s];
                }
                o4 = make_float4(r[0], r[1], r[2], r[3]);
            }
            __stcs(&out4[tid + it * T], o4);
        }

        ua = na; ub = nb; sh = nsh;
        b = bn; buf ^= 1;
    }
}

// ---------------------------------------------------------------------------
extern "C" void kernel_launch(void* const* d_in, const int* in_sizes, int n_in,
                              void* d_out, int out_size) {
    const float* logits = (const float*)d_in[0];   // (NB,)
    const float* u      = (const float*)d_in[1];   // (B, NB)
    const int*   shift  = (const int*)  d_in[2];   // (B,)

    float* masks     = (float*)d_out;                       // (B, 1, NB)
    float* log_probs = (float*)d_out + (size_t)BATCH * NB;  // (B,)

    fused_kernel<<<GRID_N, T>>>(logits, u, shift, masks, log_probs);
}

// round 6
// speedup vs baseline: 1.0779x; 1.0779x over previous
#include <cuda_runtime.h>
#include <cuda_bf16.h>
#include <math.h>
#include <cstdint>

#define NB      4096
#define PAD     (NB / 2)
#define BATCH   8192
#define T       256
#define NWARP   (T / 32)          // 8
#define GRID_N  1184              // 148 SMs * 8 CTAs/SM

// Row-invariant precomputed data.
__device__ float          g_p[NB];    // sigmoid(logits)
__device__ __nv_bfloat16  g_lb[NB];   // logits (bf16, only for the weighted sum)
__device__ float          g_C;        // sum_j log_sigmoid(-logits[j])

// ---------------------------------------------------------------------------
// Precompute: single block.
// ---------------------------------------------------------------------------
__global__ __launch_bounds__(1024)
void precompute_kernel(const float* __restrict__ logits) {
    __shared__ float s_red[32];
    const int tid = threadIdx.x;
    float acc = 0.0f;

    #pragma unroll
    for (int j = tid; j < NB; j += 1024) {
        float l = logits[j];
        g_p[j]  = 1.0f / (1.0f + expf(-l));
        g_lb[j] = __float2bfloat16(l);
        float a = fabsf(l);                       // log_sigmoid(-l), stable
        acc -= log1pf(expf(-a)) + fmaxf(l, 0.0f);
    }
    #pragma unroll
    for (int o = 16; o; o >>= 1) acc += __shfl_xor_sync(0xFFFFFFFFu, acc, o);
    if ((tid & 31) == 0) s_red[tid >> 5] = acc;
    __syncthreads();
    if (tid < 32) {
        float v = s_red[tid];
        #pragma unroll
        for (int o = 16; o; o >>= 1) v += __shfl_xor_sync(0xFFFFFFFFu, v, o);
        if (tid == 0) g_C = v;
    }
}

// ---------------------------------------------------------------------------
// Fused kernel: grid-stride, 256 threads, 8 CTAs/SM, 16 elems/thread in two
// register-friendly chunks. Byte-packed grid in double-buffered smem; one
// barrier per row. 8 independent rows per SM hide DRAM latency.
// ---------------------------------------------------------------------------
__global__ __launch_bounds__(T, 8)
void fused_kernel(const float* __restrict__ u,
                  const int*   __restrict__ shift,
                  float*       __restrict__ masks,
                  float*       __restrict__ log_probs) {
    __shared__ __align__(16) unsigned char s_g[2][NB + 16];
    __shared__ float s_red[2][NWARP];

    const int tid  = threadIdx.x;
    const int lane = tid & 31;
    const int warp = tid >> 5;

    const float4* __restrict__ p4  = (const float4*)g_p;
    const uint2*  __restrict__ lb2 = (const uint2*)g_lb;   // 4 bf16 per uint2
    const float   cC = g_C;

    int buf = 0;
    for (int b = blockIdx.x; b < BATCH; b += GRID_N, buf ^= 1) {
        const float4* __restrict__ u4 = (const float4*)(u + (size_t)b * NB);
        uint32_t* sw = (uint32_t*)&s_g[buf][0];

        float acc = 0.0f;
        // two chunks of 2 float4s each: MLP=2 within chunk, low reg pressure
        #pragma unroll
        for (int ch = 0; ch < 2; ++ch) {
            const int i0 = tid + (2 * ch)     * T;
            const int i1 = tid + (2 * ch + 1) * T;
            float4 ua = __ldcs(&u4[i0]);
            float4 ub = __ldcs(&u4[i1]);
            float4 pa = p4[i0];
            float4 pb = p4[i1];
            uint2  la = lb2[i0];
            uint2  lb = lb2[i1];
            __nv_bfloat162 la0 = *reinterpret_cast<__nv_bfloat162*>(&la.x);
            __nv_bfloat162 la1 = *reinterpret_cast<__nv_bfloat162*>(&la.y);
            __nv_bfloat162 lb0 = *reinterpret_cast<__nv_bfloat162*>(&lb.x);
            __nv_bfloat162 lb1 = *reinterpret_cast<__nv_bfloat162*>(&lb.y);

            uint32_t wa = (ua.x < pa.x ? 0x01u      : 0u)
                        | (ua.y < pa.y ? 0x100u     : 0u)
                        | (ua.z < pa.z ? 0x10000u   : 0u)
                        | (ua.w < pa.w ? 0x1000000u : 0u);
            uint32_t wb = (ub.x < pb.x ? 0x01u      : 0u)
                        | (ub.y < pb.y ? 0x100u     : 0u)
                        | (ub.z < pb.z ? 0x10000u   : 0u)
                        | (ub.w < pb.w ? 0x1000000u : 0u);
            acc += (ua.x < pa.x ? __low2float(la0)  : 0.0f)
                 + (ua.y < pa.y ? __high2float(la0) : 0.0f)
                 + (ua.z < pa.z ? __low2float(la1)  : 0.0f)
                 + (ua.w < pa.w ? __high2float(la1) : 0.0f)
                 + (ub.x < pb.x ? __low2float(lb0)  : 0.0f)
                 + (ub.y < pb.y ? __high2float(lb0) : 0.0f)
                 + (ub.z < pb.z ? __low2float(lb1)  : 0.0f)
                 + (ub.w < pb.w ? __high2float(lb1) : 0.0f);
            sw[i0] = wa;
            sw[i1] = wb;
        }

        // ---- block reduction -> log_probs[b] --------------------------------
        #pragma unroll
        for (int o = 16; o; o >>= 1) acc += __shfl_xor_sync(0xFFFFFFFFu, acc, o);
        if (lane == 0) s_red[buf][warp] = acc;
        __syncthreads();
        if (warp == 0) {
            float v = (lane < NWARP) ? s_red[buf][lane] : 0.0f;
            #pragma unroll
            for (int o = 4; o; o >>= 1) v += __shfl_xor_sync(0xFFFFFFFFu, v, o);
            if (lane == 0) log_probs[b] = v + cC;
        }

        // ---- reflect-shift gather -> 4x STG.128 ------------------------------
        const int sh = __ldg(&shift[b]);
        float4* __restrict__ out4 = (float4*)(masks + (size_t)b * NB);

        #pragma unroll
        for (int it = 0; it < 4; ++it) {
            const int idx  = tid + it * T;
            const int base = sh + 4 * idx - PAD;
            float4 o4;
            if (base >= 0 && base <= NB - 4) {
                const int wi = base >> 2;
                uint32_t w0 = sw[wi], w1 = sw[wi + 1];        // wi+1 within padding
                uint32_t pk = __byte_perm(w0, w1, 0x3210 + (base & 3) * 0x1111);
                o4.x = __int_as_float((pk & 0xFFu)         * 0x3F800000u);
                o4.y = __int_as_float(((pk >> 8)  & 0xFFu) * 0x3F800000u);
                o4.z = __int_as_float(((pk >> 16) & 0xFFu) * 0x3F800000u);
                o4.w = __int_as_float(((pk >> 24) & 0xFFu) * 0x3F800000u);
            } else {
                float r[4];
                #pragma unroll
                for (int k = 0; k < 4; k++) {
                    int s = base + k;
                    s = (s < 0) ? -s : s;
                    s = (s >= NB) ? (2 * (NB - 1) - s) : s;
                    r[k] = (float)s_g[buf][s];
                }
                o4 = make_float4(r[0], r[1], r[2], r[3]);
            }
            __stcs(&out4[idx], o4);
        }
        // double buffering removes the need for a trailing barrier per row
    }
}

// ---------------------------------------------------------------------------
extern "C" void kernel_launch(void* const* d_in, const int* in_sizes, int n_in,
                              void* d_out, int out_size) {
    const float* logits = (const float*)d_in[0];   // (NB,)
    const float* u      = (const float*)d_in[1];   // (B, NB)
    const int*   shift  = (const int*)  d_in[2];   // (B,)

    float* masks     = (float*)d_out;                       // (B, 1, NB)
    float* log_probs = (float*)d_out + (size_t)BATCH * NB;  // (B,)

    precompute_kernel<<<1, 1024>>>(logits);
    fused_kernel<<<GRID_N, T>>>(u, shift, masks, log_probs);
}